// round 4
// baseline (speedup 1.0000x reference)
#include <cuda_runtime.h>
#include <cuda_bf16.h>
#include <cstdint>

#define DD 64
#define KC 512
#define ROWSB 128
#define NTHR 256

// tcgen05 is arch-SPECIFIC: only emit on sm_103a / sm_100a family targets.
#if defined(__CUDA_ARCH__) && (defined(__CUDA_ARCH_FEAT_SM103_ALL) || defined(__CUDA_ARCH_FEAT_SM100_ALL) || defined(__CUDA_ARCH_FEAT_SM101_ALL))
#define HAS_TCGEN05 1
#else
#define HAS_TCGEN05 0
#endif

// ---- smem byte offsets (tcgen05 path) ----
#define MB_BLOAD(q)  ((q) * 8)
#define MB_MDONE(q)  (32 + (q) * 8)
#define MB_AREADY    64
#define TMEM_SLOT    96
#define A_OFF(s)     (1024 + (s) * 16384)
#define B_OFF(b, s)  (50176 + (b) * 49152 + (s) * 16384)
#define XF_OFF       148480
#define CS_OFF       181760
#define SIDX_OFF     183808
#define SMEM_TOTAL   185344

// ---- fallback layout sizes ----
#define XS_STRIDE 132
#define WS_STRIDE 516

__device__ float g_csqr[KC];
__device__ __align__(16) __nv_bfloat16 g_bh[KC * DD];
__device__ __align__(16) __nv_bfloat16 g_bl[KC * DD];
__device__ __align__(16) __nv_bfloat16 g_bq[KC * DD];

// ---------- prep: codebook norms (reference rounding order) + bf16 limbs ----------
__global__ void prep_kernel(const float* __restrict__ cbk) {
    int c = threadIdx.x;
    if (c < KC) {
        float s = 0.0f;
        for (int k = 0; k < DD; ++k) {
            float v = cbk[c * DD + k];
            s = __fadd_rn(s, __fmul_rn(v, v));
            __nv_bfloat16 h = __float2bfloat16(v);
            float r1 = v - __bfloat162float(h);
            __nv_bfloat16 l = __float2bfloat16(r1);
            float r2 = r1 - __bfloat162float(l);
            g_bh[c * DD + k] = h;
            g_bl[c * DD + k] = l;
            g_bq[c * DD + k] = __float2bfloat16(r2);
        }
        g_csqr[c] = s;
    }
}

// ---------- PTX helpers ----------
__device__ __forceinline__ uint32_t smem_u32(const void* p) {
    uint32_t a;
    asm("{ .reg .u64 t; cvta.to.shared.u64 t, %1; cvt.u32.u64 %0, t; }" : "=r"(a) : "l"(p));
    return a;
}
#if HAS_TCGEN05
__device__ __forceinline__ uint32_t elect1() {
    uint32_t p;
    asm volatile("{ .reg .pred p; elect.sync _|p, 0xFFFFFFFF; selp.b32 %0, 1, 0, p; }" : "=r"(p));
    return p;
}
__device__ __forceinline__ void mbar_init(uint32_t a, uint32_t cnt) {
    asm volatile("mbarrier.init.shared.b64 [%0], %1;" :: "r"(a), "r"(cnt) : "memory");
}
__device__ __forceinline__ void mbar_arrive(uint32_t a) {
    asm volatile("mbarrier.arrive.release.cta.shared::cta.b64 _, [%0];" :: "r"(a) : "memory");
}
__device__ __forceinline__ void mbar_wait(uint32_t a, uint32_t parity) {
    asm volatile(
        "{\n\t.reg .pred P;\n"
        "WL_%=:\n\t"
        "mbarrier.try_wait.parity.acquire.cta.shared::cta.b64 P, [%0], %1, 0x989680;\n\t"
        "@!P bra WL_%=;\n\t}"
        :: "r"(a), "r"(parity) : "memory");
}
__device__ __forceinline__ void fence_async() {
    asm volatile("fence.proxy.async.shared::cta;" ::: "memory");
}
__device__ __forceinline__ void tmem_alloc(uint32_t slot, uint32_t ncols) {
    asm volatile("tcgen05.alloc.cta_group::1.sync.aligned.shared::cta.b32 [%0], %1;"
                 :: "r"(slot), "r"(ncols) : "memory");
}
__device__ __forceinline__ void tmem_dealloc(uint32_t base, uint32_t ncols) {
    asm volatile("tcgen05.dealloc.cta_group::1.sync.aligned.b32 %0, %1;" :: "r"(base), "r"(ncols));
}
__device__ __forceinline__ void mma_f16_ss(uint32_t d, uint64_t ad, uint64_t bd,
                                           uint32_t idesc, uint32_t en) {
    asm volatile(
        "{\n\t.reg .pred p;\n\t"
        "setp.ne.u32 p, %5, 0;\n\t"
        "tcgen05.mma.cta_group::1.kind::f16 [%0], %1, %2, %3, {%4, %4, %4, %4}, p;\n\t}"
        :: "r"(d), "l"(ad), "l"(bd), "r"(idesc), "r"(0u), "r"(en) : "memory");
}
__device__ __forceinline__ void mma_commit(uint32_t mbar) {
    asm volatile("tcgen05.commit.cta_group::1.mbarrier::arrive::one.shared::cluster.b64 [%0];"
                 :: "r"(mbar) : "memory");
}
__device__ __forceinline__ void fence_tc_after() {
    asm volatile("tcgen05.fence::after_thread_sync;" ::: "memory");
}
#define LDTM_X32(r, a) \
    asm volatile("tcgen05.ld.sync.aligned.32x32b.x32.b32 " \
        "{%0,%1,%2,%3,%4,%5,%6,%7,%8,%9,%10,%11,%12,%13,%14,%15," \
        "%16,%17,%18,%19,%20,%21,%22,%23,%24,%25,%26,%27,%28,%29,%30,%31}, [%32];" \
        : "=r"((r)[0]),"=r"((r)[1]),"=r"((r)[2]),"=r"((r)[3]),"=r"((r)[4]),"=r"((r)[5]), \
          "=r"((r)[6]),"=r"((r)[7]),"=r"((r)[8]),"=r"((r)[9]),"=r"((r)[10]),"=r"((r)[11]), \
          "=r"((r)[12]),"=r"((r)[13]),"=r"((r)[14]),"=r"((r)[15]),"=r"((r)[16]),"=r"((r)[17]), \
          "=r"((r)[18]),"=r"((r)[19]),"=r"((r)[20]),"=r"((r)[21]),"=r"((r)[22]),"=r"((r)[23]), \
          "=r"((r)[24]),"=r"((r)[25]),"=r"((r)[26]),"=r"((r)[27]),"=r"((r)[28]),"=r"((r)[29]), \
          "=r"((r)[30]),"=r"((r)[31]) : "r"(a))
__device__ __forceinline__ void tmem_wait_ld() {
    asm volatile("tcgen05.wait::ld.sync.aligned;" ::: "memory");
}
#endif  // HAS_TCGEN05

__device__ __forceinline__ uint32_t sw128(uint32_t off) { return off ^ ((off >> 3) & 0x70); }

// SW128 K-major descriptor base (layout=2, version=1, SBO=64, LBO=1)
#define DESC_BASE 0x4000404000010000ULL
__device__ __forceinline__ uint64_t mk_desc(uint32_t addr) {
    return DESC_BASE | ((uint64_t)(addr >> 4) & 0x3FFF);
}

// idesc: fp32 acc, bf16 a/b, N=128, M=128
#define IDESC 0x8200490u

// f32x2 helpers for the fallback path
__device__ __forceinline__ unsigned long long pack2(float lo, float hi) {
    unsigned long long r;
    asm("mov.b64 %0, {%1, %2};" : "=l"(r) : "f"(lo), "f"(hi));
    return r;
}
__device__ __forceinline__ void unpack2(unsigned long long v, float& lo, float& hi) {
    asm("mov.b64 {%0, %1}, %2;" : "=f"(lo), "=f"(hi) : "l"(v));
}
__device__ __forceinline__ void fma2(unsigned long long& acc, unsigned long long a,
                                     unsigned long long b) {
    asm("fma.rn.f32x2 %0, %1, %2, %0;" : "+l"(acc) : "l"(a), "l"(b));
}

__global__ void __launch_bounds__(NTHR, 1)
vq_mma(const float* __restrict__ x, const float* __restrict__ cbk,
       float* __restrict__ out, int n) {
    extern __shared__ char smem[];
    const int tid = threadIdx.x;
    const int rowbase = blockIdx.x * ROWSB;
    const size_t nD = (size_t)n * DD;

#if HAS_TCGEN05
    // ================= tcgen05 path =================
    const uint32_t sb = smem_u32(smem);
    const int wid = tid >> 5;
    float* Xf = (float*)(smem + XF_OFF);
    float* Cs = (float*)(smem + CS_OFF);
    int* sidx = (int*)(smem + SIDX_OFF);

    if (tid == 0) {
        for (int q = 0; q < 4; ++q) { mbar_init(sb + MB_BLOAD(q), 96); mbar_init(sb + MB_MDONE(q), 1); }
        mbar_init(sb + MB_AREADY, 128);
    }
    __syncthreads();
    if (wid == 7) tmem_alloc(sb + TMEM_SLOT, 512);
    __syncthreads();
    const uint32_t tmem = *(volatile uint32_t*)(smem + TMEM_SLOT);

    if (wid < 4) {
        // ---- A phase: stage x tile, compute xsq + bf16 splits ----
        for (int i = 0; i < 16; ++i) {
            int e4 = tid + i * 128;
            int r = e4 >> 4, kq = e4 & 15;
            float4 v = make_float4(0.f, 0.f, 0.f, 0.f);
            if (rowbase + r < n) v = ((const float4*)x)[(size_t)(rowbase + r) * 16 + kq];
            float* d = Xf + r * 65 + kq * 4;
            d[0] = v.x; d[1] = v.y; d[2] = v.z; d[3] = v.w;
        }
        asm volatile("bar.sync 1, 128;" ::: "memory");
        const int row = tid;
        float xs = 0.0f;
        for (int k = 0; k < DD; k += 2) {
            float v0 = Xf[row * 65 + k], v1 = Xf[row * 65 + k + 1];
            xs = __fadd_rn(xs, __fmul_rn(v0, v0));
            xs = __fadd_rn(xs, __fmul_rn(v1, v1));
            __nv_bfloat16 h0 = __float2bfloat16(v0);
            float r10 = v0 - __bfloat162float(h0);
            __nv_bfloat16 l0 = __float2bfloat16(r10);
            __nv_bfloat16 q0 = __float2bfloat16(r10 - __bfloat162float(l0));
            __nv_bfloat16 h1 = __float2bfloat16(v1);
            float r11 = v1 - __bfloat162float(h1);
            __nv_bfloat16 l1 = __float2bfloat16(r11);
            __nv_bfloat16 q1 = __float2bfloat16(r11 - __bfloat162float(l1));
            uint32_t wh = (uint32_t)__bfloat16_as_ushort(h0) | ((uint32_t)__bfloat16_as_ushort(h1) << 16);
            uint32_t wl = (uint32_t)__bfloat16_as_ushort(l0) | ((uint32_t)__bfloat16_as_ushort(l1) << 16);
            uint32_t wq = (uint32_t)__bfloat16_as_ushort(q0) | ((uint32_t)__bfloat16_as_ushort(q1) << 16);
            uint32_t so = sw128(row * 128 + k * 2);
            *(uint32_t*)(smem + A_OFF(0) + so) = wh;
            *(uint32_t*)(smem + A_OFF(1) + so) = wl;
            *(uint32_t*)(smem + A_OFF(2) + so) = wq;
        }
        Cs[row] = g_csqr[row]; Cs[row + 128] = g_csqr[row + 128];
        Cs[row + 256] = g_csqr[row + 256]; Cs[row + 384] = g_csqr[row + 384];
        asm volatile("bar.sync 1, 128;" ::: "memory");
        fence_async();
        mbar_arrive(sb + MB_AREADY);

        // ---- epilogue pass 1: approx min over all 512 codes ----
        float amin = 3.4e38f;
        for (int q = 0; q < 4; ++q) {
            mbar_wait(sb + MB_MDONE(q), 0);
            fence_tc_after();
            for (int b = 0; b < 4; ++b) {
                uint32_t rg[32];
                LDTM_X32(rg, tmem + q * 128 + b * 32);
                tmem_wait_ld();
                const int base = q * 128 + b * 32;
                #pragma unroll
                for (int j = 0; j < 32; ++j) {
                    float dot = __uint_as_float(rg[j]);
                    float t = __fadd_rn(xs, Cs[base + j]);
                    float dist = __fmaf_rn(-2.0f, dot, t);
                    if (dist < amin) amin = dist;
                }
            }
        }

        // ---- epilogue pass 2: exact refine of near-min candidates ----
        // Margin covers approx-dot error (~1e-7) + fp32 dist quantization (ulp(64)=7.6e-6).
        const float thr = amin + 3e-5f;
        float best = 3.4e38f;
        int bi = 0;
        for (int q = 0; q < 4; ++q) {
            for (int b = 0; b < 4; ++b) {
                uint32_t rg[32];
                LDTM_X32(rg, tmem + q * 128 + b * 32);
                tmem_wait_ld();
                const int base = q * 128 + b * 32;
                #pragma unroll 4
                for (int j = 0; j < 32; ++j) {
                    float dot = __uint_as_float(rg[j]);
                    float t = __fadd_rn(xs, Cs[base + j]);
                    float adist = __fmaf_rn(-2.0f, dot, t);
                    if (adist <= thr) {
                        // Exact reference-rounded distance (same arithmetic that gave
                        // rel_err 0.0 in R1): sequential fmaf dot, single-rounding fold.
                        const int code = base + j;
                        const float* crow = cbk + code * DD;
                        float ed = 0.0f;
                        #pragma unroll 8
                        for (int k = 0; k < DD; ++k)
                            ed = __fmaf_rn(Xf[row * 65 + k], __ldg(crow + k), ed);
                        float dist = __fmaf_rn(-2.0f, ed, t);
                        // ascending code order + strict < == lowest-index tie-break
                        if (dist < best) { best = dist; bi = code; }
                    }
                }
            }
        }
        sidx[row] = bi;
        if (rowbase + row < n) out[2 * nD + rowbase + row] = (float)bi;
    } else if (wid < 7) {
        // ---- B loaders: 96 threads, double-buffered quarters ----
        const int lt = tid - 128;
        const __nv_bfloat16* gsrc[3] = { g_bh, g_bl, g_bq };
        for (int q = 0; q < 4; ++q) {
            if (q >= 2) mbar_wait(sb + MB_MDONE(q - 2), 0);
            const int buf = q & 1;
            for (int i = 0; i < 32; ++i) {
                int c = lt + i * 96;
                int s = c >> 10, r = (c >> 3) & 127, kc = c & 7;
                uint4 v = ((const uint4*)gsrc[s])[(size_t)(q * 128 + r) * 8 + kc];
                *(uint4*)(smem + B_OFF(buf, s) + sw128(r * 128 + kc * 16)) = v;
            }
            fence_async();
            mbar_arrive(sb + MB_BLOAD(q));
        }
    } else {
        // ---- MMA issuer (warp 7, one elected thread) ----
        if (elect1()) {
            mbar_wait(sb + MB_AREADY, 0);
            uint64_t adesc[3] = { mk_desc(sb + A_OFF(0)), mk_desc(sb + A_OFF(1)), mk_desc(sb + A_OFF(2)) };
            const int pa[6] = { 0, 0, 1, 1, 0, 2 };
            const int pb[6] = { 0, 1, 0, 1, 2, 0 };
            for (int q = 0; q < 4; ++q) {
                mbar_wait(sb + MB_BLOAD(q), 0);
                fence_async();
                const int buf = q & 1;
                const uint32_t dcol = tmem + q * 128;
                for (int p = 0; p < 6; ++p) {
                    uint64_t ad = adesc[pa[p]];
                    uint64_t bd = mk_desc(sb + B_OFF(buf, pb[p]));
                    #pragma unroll
                    for (int k = 0; k < 4; ++k)
                        mma_f16_ss(dcol, ad + k * 2, bd + k * 2, IDESC, (p | k) != 0);
                }
                mma_commit(sb + MB_MDONE(q));
            }
        }
    }

    __syncthreads();
    for (int i = tid; i < ROWSB * 16; i += NTHR) {
        int row = i >> 4, qd = i & 15;
        int gr = rowbase + row;
        if (gr < n) {
            float4 v = ((const float4*)cbk)[sidx[row] * 16 + qd];
            ((float4*)(out + (size_t)gr * DD))[qd] = v;
            ((float4*)(out + nD + (size_t)gr * DD))[qd] = v;
        }
    }
    __syncthreads();
    if (wid == 7) tmem_dealloc(tmem, 512);

#else
    // ================= fallback: proven R1 FFMA kernel =================
    float* smem_f = (float*)smem;
    float* Ws   = smem_f;
    float* Xs   = Ws + DD * WS_STRIDE;
    float* Cs   = Xs + DD * XS_STRIDE;
    float* redv = Cs + KC;
    int*   redi = (int*)(redv + ROWSB * 16);
    int*   sidx = redi + ROWSB * 16;

    for (int e4 = tid; e4 < KC * DD / 4; e4 += NTHR) {
        int e = e4 * 4;
        int code = e >> 6, k = e & 63;
        float4 v = ((const float4*)cbk)[e4];
        Ws[(k + 0) * WS_STRIDE + code] = v.x;
        Ws[(k + 1) * WS_STRIDE + code] = v.y;
        Ws[(k + 2) * WS_STRIDE + code] = v.z;
        Ws[(k + 3) * WS_STRIDE + code] = v.w;
    }
    for (int e4 = tid; e4 < ROWSB * DD / 4; e4 += NTHR) {
        int e = e4 * 4;
        int r = e >> 6, k = e & 63;
        int gr = rowbase + r;
        float4 v = make_float4(0.f, 0.f, 0.f, 0.f);
        if (gr < n) v = ((const float4*)x)[(size_t)gr * (DD / 4) + (k >> 2)];
        Xs[(k + 0) * XS_STRIDE + r] = v.x;
        Xs[(k + 1) * XS_STRIDE + r] = v.y;
        Xs[(k + 2) * XS_STRIDE + r] = v.z;
        Xs[(k + 3) * XS_STRIDE + r] = v.w;
    }
    for (int c = tid; c < KC; c += NTHR) Cs[c] = g_csqr[c];
    __syncthreads();

    const int rowT = tid & 15;
    const int codeT = tid >> 4;
    const int r0 = rowT * 8;
    const int c0 = codeT * 32;

    float xsq[8];
    #pragma unroll
    for (int rr = 0; rr < 8; ++rr) {
        float s = 0.0f;
        for (int k = 0; k < DD; ++k) {
            float v = Xs[k * XS_STRIDE + r0 + rr];
            s = __fadd_rn(s, __fmul_rn(v, v));
        }
        xsq[rr] = s;
    }

    float bestv[8];
    int besti[8];
    #pragma unroll
    for (int rr = 0; rr < 8; ++rr) { bestv[rr] = 3.4e38f; besti[rr] = 0; }

    for (int chunk = 0; chunk < 4; ++chunk) {
        const int cb0 = c0 + chunk * 8;
        unsigned long long acc[4][8];
        #pragma unroll
        for (int rp = 0; rp < 4; ++rp)
            #pragma unroll
            for (int cc = 0; cc < 8; ++cc) acc[rp][cc] = 0ULL;

        #pragma unroll 4
        for (int k = 0; k < DD; ++k) {
            const float* xrow = Xs + k * XS_STRIDE + r0;
            unsigned long long x2[4];
            #pragma unroll
            for (int rp = 0; rp < 4; ++rp)
                x2[rp] = *(const unsigned long long*)(xrow + rp * 2);
            const float* wrow = Ws + k * WS_STRIDE + cb0;
            float4 wa = *(const float4*)(wrow);
            float4 wb = *(const float4*)(wrow + 4);
            float w[8] = {wa.x, wa.y, wa.z, wa.w, wb.x, wb.y, wb.z, wb.w};
            #pragma unroll
            for (int cc = 0; cc < 8; ++cc) {
                unsigned long long w2 = pack2(w[cc], w[cc]);
                #pragma unroll
                for (int rp = 0; rp < 4; ++rp) fma2(acc[rp][cc], x2[rp], w2);
            }
        }

        #pragma unroll
        for (int cc = 0; cc < 8; ++cc) {
            const int code = cb0 + cc;
            const float cs = Cs[code];
            #pragma unroll
            for (int rp = 0; rp < 4; ++rp) {
                float d0, d1;
                unpack2(acc[rp][cc], d0, d1);
                float t0 = __fadd_rn(xsq[rp * 2 + 0], cs);
                float t1 = __fadd_rn(xsq[rp * 2 + 1], cs);
                float dist0 = __fmaf_rn(-2.0f, d0, t0);
                float dist1 = __fmaf_rn(-2.0f, d1, t1);
                if (dist0 < bestv[rp * 2 + 0]) { bestv[rp * 2 + 0] = dist0; besti[rp * 2 + 0] = code; }
                if (dist1 < bestv[rp * 2 + 1]) { bestv[rp * 2 + 1] = dist1; besti[rp * 2 + 1] = code; }
            }
        }
    }

    #pragma unroll
    for (int rr = 0; rr < 8; ++rr) {
        redv[(r0 + rr) * 16 + codeT] = bestv[rr];
        redi[(r0 + rr) * 16 + codeT] = besti[rr];
    }
    __syncthreads();

    if (tid < ROWSB) {
        int row = tid;
        float bv = redv[row * 16 + 0];
        int bi = redi[row * 16 + 0];
        #pragma unroll
        for (int ct = 1; ct < 16; ++ct) {
            float v = redv[row * 16 + ct];
            int i2 = redi[row * 16 + ct];
            if (v < bv) { bv = v; bi = i2; }
        }
        sidx[row] = bi;
        int gr = rowbase + row;
        if (gr < n) out[2 * nD + gr] = (float)bi;
    }
    __syncthreads();

    for (int i = tid; i < ROWSB * (DD / 4); i += NTHR) {
        int row = i >> 4, q = i & 15;
        int gr = rowbase + row;
        if (gr < n) {
            float4 v = ((const float4*)cbk)[sidx[row] * (DD / 4) + q];
            ((float4*)(out + (size_t)gr * DD))[q] = v;
            ((float4*)(out + nD + (size_t)gr * DD))[q] = v;
        }
    }
#endif
}

extern "C" void kernel_launch(void* const* d_in, const int* in_sizes, int n_in,
                              void* d_out, int out_size) {
    const float* x = (const float*)d_in[0];
    const float* cbk = (const float*)d_in[1];
    float* out = (float*)d_out;
    const int n = in_sizes[0] / DD;

    cudaFuncSetAttribute(vq_mma, cudaFuncAttributeMaxDynamicSharedMemorySize, SMEM_TOTAL);
    prep_kernel<<<1, KC>>>(cbk);
    int grid = (n + ROWSB - 1) / ROWSB;
    vq_mma<<<grid, NTHR, SMEM_TOTAL>>>(x, cbk, out, n);
}